// round 3
// baseline (speedup 1.0000x reference)
#include <cuda_runtime.h>

#define NCHUNK 32
#define CPC    16          // channels per chunk (512 / 32)
#define CH     512
#define HW     4096        // 64*64
#define NPIX   32768       // 8 * 4096

// Static device scratch (no dynamic allocation allowed).
__device__ __align__(16) float g_p1[NCHUNK][NPIX];
__device__ __align__(16) float g_p2[NCHUNK][NPIX];
__device__ float g_recon[NPIX];
__device__ float g_ref[NPIX];

// ---- packed f32x2 helpers (Blackwell FFMA2 path, PTX-only) -----------------
__device__ __forceinline__ unsigned long long pk2(float lo, float hi) {
    unsigned long long r;
    asm("mov.b64 %0, {%1, %2};" : "=l"(r) : "f"(lo), "f"(hi));
    return r;
}
__device__ __forceinline__ void unpk2(unsigned long long v, float& lo, float& hi) {
    asm("mov.b64 {%0, %1}, %2;" : "=f"(lo), "=f"(hi) : "l"(v));
}
__device__ __forceinline__ unsigned long long fma2(unsigned long long a,
                                                   unsigned long long b,
                                                   unsigned long long c) {
    unsigned long long d;
    asm("fma.rn.f32x2 %0, %1, %2, %3;" : "=l"(d) : "l"(a), "l"(b), "l"(c));
    return d;
}
__device__ __forceinline__ unsigned long long mul2(unsigned long long a,
                                                   unsigned long long b) {
    unsigned long long d;
    asm("mul.rn.f32x2 %0, %1, %2;" : "=l"(d) : "l"(a), "l"(b));
    return d;
}

// ---------------------------------------------------------------------------
// Kernel A: partial channel dot-products.
// grid (32, 32): x = pixel tile of 1024, y = channel chunk of 16. 1024 blocks,
// 8192 warps total -> 48 warps/SM resident (75% occ), DRAM-latency covered.
// ---------------------------------------------------------------------------
__global__ void __launch_bounds__(256) k_dot(
        const float* __restrict__ spade, const float* __restrict__ x,
        const float* __restrict__ w1, const float* __restrict__ w2) {
    __shared__ float sw1[CPC], sw2[CPC];
    const int t = threadIdx.x;
    const int chunk = blockIdx.y;
    if (t < CPC)            sw1[t]       = w1[chunk * CPC + t];
    else if (t < 2 * CPC)   sw2[t - CPC] = w2[chunk * CPC + t - CPC];
    __syncthreads();

    const int P  = blockIdx.x * 1024 + t * 4;     // global pixel base (4 px)
    const int b  = P >> 12;
    const int hw = P & (HW - 1);
    const size_t base = (size_t)b * CH * HW + (size_t)chunk * CPC * HW + hw;
    const float* fp = spade + base;
    const float* xp = x + base;

    float4 a1 = make_float4(0.f, 0.f, 0.f, 0.f);
    float4 a2 = make_float4(0.f, 0.f, 0.f, 0.f);
    #pragma unroll 8
    for (int c = 0; c < CPC; c++) {
        float4 f = *(const float4*)(fp + (size_t)c * HW);
        float4 v = *(const float4*)(xp + (size_t)c * HW);
        const float u = sw1[c];
        const float w = sw2[c];
        a1.x += f.x * u; a1.y += f.y * u; a1.z += f.z * u; a1.w += f.w * u;
        a2.x += v.x * w; a2.y += v.y * w; a2.z += v.z * w; a2.w += v.w * w;
    }
    *(float4*)&g_p1[chunk][P] = a1;
    *(float4*)&g_p2[chunk][P] = a2;
}

// ---------------------------------------------------------------------------
// Kernel B: reduce 32 chunk partials + bias + ReLU (float4, L2-resident).
// grid 64 x 128 threads, 4 pixels per thread.
// ---------------------------------------------------------------------------
__global__ void __launch_bounds__(128) k_reduce(
        const float* __restrict__ b1, const float* __restrict__ b2) {
    const int P = (blockIdx.x * 128 + threadIdx.x) * 4;
    const float bb1 = b1[0], bb2 = b2[0];
    float4 s1 = make_float4(bb1, bb1, bb1, bb1);
    float4 s2 = make_float4(bb2, bb2, bb2, bb2);
    #pragma unroll
    for (int k = 0; k < NCHUNK; k++) {
        float4 a = *(const float4*)&g_p1[k][P];
        float4 c = *(const float4*)&g_p2[k][P];
        s1.x += a.x; s1.y += a.y; s1.z += a.z; s1.w += a.w;
        s2.x += c.x; s2.y += c.y; s2.z += c.z; s2.w += c.w;
    }
    s1.x = fmaxf(s1.x, 0.f); s1.y = fmaxf(s1.y, 0.f);
    s1.z = fmaxf(s1.z, 0.f); s1.w = fmaxf(s1.w, 0.f);
    s2.x = fmaxf(s2.x, 0.f); s2.y = fmaxf(s2.y, 0.f);
    s2.z = fmaxf(s2.z, 0.f); s2.w = fmaxf(s2.w, 0.f);
    *(float4*)&g_recon[P] = s1;
    *(float4*)&g_ref[P]   = s2;
}

// ---------------------------------------------------------------------------
// Kernel C: per-patch 2x2 correlation + first-occurrence argmax + gather.
// grid 512: block = (b, group of 16 patches), 8 warps x 2 patches.
// Two SMEM tiles: Ra (map) and Rs (column-shifted map) -> no SHFL in the
// inner loop, pure LDS.64 + packed FFMA2. Four independent argmax
// accumulators (one per unroll slot) break the serial compare chain;
// merged at the end with explicit index tie-break (first occurrence).
// ---------------------------------------------------------------------------
__global__ void __launch_bounds__(256) k_match(float* __restrict__ out) {
    __shared__ float Ra[65][66];   // Ra[r][c] = recon(r,c), zero padded
    __shared__ float Rs[65][66];   // Rs[r][c] = recon(r,c+1), zero padded
    const int t    = threadIdx.x;
    const int b    = blockIdx.x >> 6;
    const int grp  = blockIdx.x & 63;
    const float* rb = g_recon + b * HW;

    for (int i = t; i < 65 * 66; i += 256) {
        const int row = i / 66;
        const int col = i - row * 66;
        const bool in  = (row < 64) && (col < 64);
        const bool ins = (row < 64) && (col + 1 < 64);
        Ra[row][col] = in  ? rb[row * 64 + col]     : 0.f;
        Rs[row][col] = ins ? rb[row * 64 + col + 1] : 0.f;
    }
    __syncthreads();

    const int lane = t & 31;
    const int w    = t >> 5;
    const float* refb = g_ref + b * HW;

    for (int k = 0; k < 2; k++) {
        const int l  = grp * 16 + w * 2 + k;
        const int pi = l >> 5;
        const int pj = l & 31;
        // 2x2 "kernel" from the reference map (broadcast loads)
        const float c00 = refb[(2 * pi) * 64 + 2 * pj];
        const float c01 = refb[(2 * pi) * 64 + 2 * pj + 1];
        const float c10 = refb[(2 * pi + 1) * 64 + 2 * pj];
        const float c11 = refb[(2 * pi + 1) * 64 + 2 * pj + 1];
        const unsigned long long cc00 = pk2(c00, c00);
        const unsigned long long cc01 = pk2(c01, c01);
        const unsigned long long cc10 = pk2(c10, c10);
        const unsigned long long cc11 = pk2(c11, c11);

        const int q = lane * 2;
        float2 a0 = *(const float2*)&Ra[0][q];
        float2 s0 = *(const float2*)&Rs[0][q];

        // 4 independent (value, idx) accumulators; all y >= 0 so -1 sentinel.
        float bv[4] = {-1.f, -1.f, -1.f, -1.f};
        int   bi[4] = {0, 0, 0, 0};

        #pragma unroll
        for (int p0 = 0; p0 < 64; p0 += 4) {
            #pragma unroll
            for (int j = 0; j < 4; j++) {
                const int p = p0 + j;
                float2 a1 = *(const float2*)&Ra[p + 1][q];
                float2 s1 = *(const float2*)&Rs[p + 1][q];
                unsigned long long yp =
                    fma2(cc11, pk2(s1.x, s1.y),
                    fma2(cc10, pk2(a1.x, a1.y),
                    fma2(cc01, pk2(s0.x, s0.y),
                    mul2(cc00, pk2(a0.x, a0.y)))));
                float y0, y1;
                unpk2(yp, y0, y1);
                // row candidate: keep earlier (y0) on tie
                const int   idx = (p << 6) + q;
                const bool  g   = (y1 > y0);
                const float rv  = g ? y1 : y0;
                const int   ri  = idx + (g ? 1 : 0);
                // accumulator: strictly-greater keeps earlier row on tie
                if (rv > bv[j]) { bv[j] = rv; bi[j] = ri; }
                a0 = a1; s0 = s1;
            }
        }

        // Merge 4 accumulators; explicit idx tie-break (first occurrence).
        float bestv = bv[0];
        int   besti = bi[0];
        #pragma unroll
        for (int j = 1; j < 4; j++) {
            if (bv[j] > bestv || (bv[j] == bestv && bi[j] < besti)) {
                bestv = bv[j]; besti = bi[j];
            }
        }

        // Warp argmax; ties -> smallest flat index (matches jnp.argmax).
        for (int off = 16; off; off >>= 1) {
            const float v2 = __shfl_down_sync(0xffffffffu, bestv, off);
            const int   i2 = __shfl_down_sync(0xffffffffu, besti, off);
            if (v2 > bestv || (v2 == bestv && i2 < besti)) { bestv = v2; besti = i2; }
        }

        if (lane == 0) {
            const int g  = besti >> 2;      // offset // 4
            const int gi = g >> 5;
            const int gj = g & 31;
            float* o = out + b * HW + (2 * pi) * 64 + 2 * pj;
            o[0]  = Ra[2 * gi][2 * gj];
            o[1]  = Ra[2 * gi][2 * gj + 1];
            o[64] = Ra[2 * gi + 1][2 * gj];
            o[65] = Ra[2 * gi + 1][2 * gj + 1];
        }
    }
}

extern "C" void kernel_launch(void* const* d_in, const int* in_sizes, int n_in,
                              void* d_out, int out_size) {
    const float* spade = (const float*)d_in[0];
    const float* x     = (const float*)d_in[1];
    const float* w1    = (const float*)d_in[2];
    const float* b1    = (const float*)d_in[3];
    const float* w2    = (const float*)d_in[4];
    const float* b2    = (const float*)d_in[5];
    float* out = (float*)d_out;

    k_dot<<<dim3(32, NCHUNK), 256>>>(spade, x, w1, w2);
    k_reduce<<<64, 128>>>(b1, b2);
    k_match<<<512, 256>>>(out);
}

// round 4
// speedup vs baseline: 1.6588x; 1.6588x over previous
#include <cuda_runtime.h>

#define NCHUNK 16
#define CPC    32          // channels per chunk (512 / 16)
#define CH     512
#define HW     4096        // 64*64
#define NPIX   32768       // 8 * 4096

// Static device scratch (no dynamic allocation allowed).
__device__ __align__(16) float g_p1[NCHUNK][NPIX];
__device__ __align__(16) float g_p2[NCHUNK][NPIX];
__device__ float g_recon[NPIX];
__device__ float g_ref[NPIX];

// ---- packed f32x2 helpers (Blackwell FFMA2 path, PTX-only) -----------------
__device__ __forceinline__ unsigned long long pk2(float lo, float hi) {
    unsigned long long r;
    asm("mov.b64 %0, {%1, %2};" : "=l"(r) : "f"(lo), "f"(hi));
    return r;
}
__device__ __forceinline__ void unpk2(unsigned long long v, float& lo, float& hi) {
    asm("mov.b64 {%0, %1}, %2;" : "=f"(lo), "=f"(hi) : "l"(v));
}
__device__ __forceinline__ unsigned long long fma2(unsigned long long a,
                                                   unsigned long long b,
                                                   unsigned long long c) {
    unsigned long long d;
    asm("fma.rn.f32x2 %0, %1, %2, %3;" : "=l"(d) : "l"(a), "l"(b), "l"(c));
    return d;
}
__device__ __forceinline__ unsigned long long mul2(unsigned long long a,
                                                   unsigned long long b) {
    unsigned long long d;
    asm("mul.rn.f32x2 %0, %1, %2;" : "=l"(d) : "l"(a), "l"(b));
    return d;
}

// ---------------------------------------------------------------------------
// Kernel A: partial channel dot-products.
// grid (32, 16) = 512 blocks = exactly ONE wave at ~3.5 blocks/SM (40% occ) —
// R2-measured best. __ldcs: inputs are read-once, keep them out of L2 so the
// scratch partials stay resident for k_reduce.
// ---------------------------------------------------------------------------
__global__ void __launch_bounds__(256) k_dot(
        const float* __restrict__ spade, const float* __restrict__ x,
        const float* __restrict__ w1, const float* __restrict__ w2) {
    __shared__ float sw1[CPC], sw2[CPC];
    const int t = threadIdx.x;
    const int chunk = blockIdx.y;
    if (t < CPC)            sw1[t]       = w1[chunk * CPC + t];
    else if (t < 2 * CPC)   sw2[t - CPC] = w2[chunk * CPC + t - CPC];
    __syncthreads();

    const int P  = blockIdx.x * 1024 + t * 4;     // global pixel base (4 px)
    const int b  = P >> 12;
    const int hw = P & (HW - 1);
    const size_t base = (size_t)b * CH * HW + (size_t)chunk * CPC * HW + hw;
    const float4* fp = (const float4*)(spade + base);
    const float4* xp = (const float4*)(x + base);

    float4 a1 = make_float4(0.f, 0.f, 0.f, 0.f);
    float4 a2 = make_float4(0.f, 0.f, 0.f, 0.f);
    #pragma unroll 8
    for (int c = 0; c < CPC; c++) {
        float4 f = __ldcs(fp + (size_t)c * (HW / 4));
        float4 v = __ldcs(xp + (size_t)c * (HW / 4));
        const float u = sw1[c];
        const float w = sw2[c];
        a1.x += f.x * u; a1.y += f.y * u; a1.z += f.z * u; a1.w += f.w * u;
        a2.x += v.x * w; a2.y += v.y * w; a2.z += v.z * w; a2.w += v.w * w;
    }
    *(float4*)&g_p1[chunk][P] = a1;
    *(float4*)&g_p2[chunk][P] = a2;
}

// ---------------------------------------------------------------------------
// Kernel B: reduce 16 chunk partials + bias + ReLU -> recon / reference maps.
// 128 blocks x 256 threads, scalar coalesced (R2-proven shape).
// ---------------------------------------------------------------------------
__global__ void __launch_bounds__(256) k_reduce(
        const float* __restrict__ b1, const float* __restrict__ b2) {
    const int P = blockIdx.x * 256 + threadIdx.x;
    float s1 = b1[0];
    float s2 = b2[0];
    #pragma unroll
    for (int k = 0; k < NCHUNK; k++) {
        s1 += g_p1[k][P];
        s2 += g_p2[k][P];
    }
    g_recon[P] = fmaxf(s1, 0.f);
    g_ref[P]   = fmaxf(s2, 0.f);
}

// ---------------------------------------------------------------------------
// Kernel C: per-patch 2x2 correlation + first-occurrence argmax + gather.
// grid 512: block = (b, group of 16 patches), 8 warps x 2 patches.
// Ra = recon tile (padded), Rs = column-shifted tile -> inner loop is pure
// 2x LDS.64 + 4 packed FFMA2, no SHFL. Two alternating argmax accumulators
// (even/odd rows) halve the serial compare chain; merged with explicit idx
// tie-break so jnp.argmax first-occurrence semantics hold.
// ---------------------------------------------------------------------------
__global__ void __launch_bounds__(256) k_match(float* __restrict__ out) {
    __shared__ float Ra[65][66];   // Ra[r][c] = recon(r,c);   zero padded
    __shared__ float Rs[65][66];   // Rs[r][c] = recon(r,c+1); zero padded
    const int t    = threadIdx.x;
    const int b    = blockIdx.x >> 6;
    const int grp  = blockIdx.x & 63;
    const float* rb = g_recon + b * HW;

    for (int i = t; i < 65 * 66; i += 256) {
        const int row = i / 66;
        const int col = i - row * 66;
        const bool in  = (row < 64) && (col < 64);
        const bool ins = (row < 64) && (col < 63);
        Ra[row][col] = in  ? rb[row * 64 + col]     : 0.f;
        Rs[row][col] = ins ? rb[row * 64 + col + 1] : 0.f;
    }
    __syncthreads();

    const int lane = t & 31;
    const int w    = t >> 5;
    const float* refb = g_ref + b * HW;

    for (int k = 0; k < 2; k++) {
        const int l  = grp * 16 + w * 2 + k;
        const int pi = l >> 5;
        const int pj = l & 31;
        // 2x2 "kernel" from the reference map (broadcast loads)
        const float c00 = refb[(2 * pi) * 64 + 2 * pj];
        const float c01 = refb[(2 * pi) * 64 + 2 * pj + 1];
        const float c10 = refb[(2 * pi + 1) * 64 + 2 * pj];
        const float c11 = refb[(2 * pi + 1) * 64 + 2 * pj + 1];
        const unsigned long long cc00 = pk2(c00, c00);
        const unsigned long long cc01 = pk2(c01, c01);
        const unsigned long long cc10 = pk2(c10, c10);
        const unsigned long long cc11 = pk2(c11, c11);

        const int q = lane * 2;
        float2 a0 = *(const float2*)&Ra[0][q];
        float2 s0 = *(const float2*)&Rs[0][q];

        // two independent (value, idx) accumulators; all y >= 0 so -1 sentinel
        float bv0 = -1.f, bv1 = -1.f;
        int   bi0 = 0,    bi1 = 0;
        int   idxp = q;                    // rolling flat index (p<<6) + q

        #pragma unroll 4
        for (int p = 0; p < 64; p += 2) {
            // even row p  -> accumulator 0
            {
                float2 a1 = *(const float2*)&Ra[p + 1][q];
                float2 s1 = *(const float2*)&Rs[p + 1][q];
                unsigned long long yp =
                    fma2(cc11, pk2(s1.x, s1.y),
                    fma2(cc10, pk2(a1.x, a1.y),
                    fma2(cc01, pk2(s0.x, s0.y),
                    mul2(cc00, pk2(a0.x, a0.y)))));
                float y0, y1; unpk2(yp, y0, y1);
                const bool  g  = (y1 > y0);
                const float rv = g ? y1 : y0;
                const int   ri = idxp + (g ? 1 : 0);
                if (rv > bv0) { bv0 = rv; bi0 = ri; }
                a0 = a1; s0 = s1; idxp += 64;
            }
            // odd row p+1 -> accumulator 1
            {
                float2 a1 = *(const float2*)&Ra[p + 2][q];
                float2 s1 = *(const float2*)&Rs[p + 2][q];
                unsigned long long yp =
                    fma2(cc11, pk2(s1.x, s1.y),
                    fma2(cc10, pk2(a1.x, a1.y),
                    fma2(cc01, pk2(s0.x, s0.y),
                    mul2(cc00, pk2(a0.x, a0.y)))));
                float y0, y1; unpk2(yp, y0, y1);
                const bool  g  = (y1 > y0);
                const float rv = g ? y1 : y0;
                const int   ri = idxp + (g ? 1 : 0);
                if (rv > bv1) { bv1 = rv; bi1 = ri; }
                a0 = a1; s0 = s1; idxp += 64;
            }
        }

        // Merge accumulators; explicit idx tie-break (first occurrence).
        float bestv = bv0;
        int   besti = bi0;
        if (bv1 > bestv || (bv1 == bestv && bi1 < besti)) { bestv = bv1; besti = bi1; }

        // Warp argmax; ties -> smallest flat index (matches jnp.argmax).
        for (int off = 16; off; off >>= 1) {
            const float v2 = __shfl_down_sync(0xffffffffu, bestv, off);
            const int   i2 = __shfl_down_sync(0xffffffffu, besti, off);
            if (v2 > bestv || (v2 == bestv && i2 < besti)) { bestv = v2; besti = i2; }
        }

        if (lane == 0) {
            const int g  = besti >> 2;      // offset // 4
            const int gi = g >> 5;
            const int gj = g & 31;
            float* o = out + b * HW + (2 * pi) * 64 + 2 * pj;
            o[0]  = Ra[2 * gi][2 * gj];
            o[1]  = Ra[2 * gi][2 * gj + 1];
            o[64] = Ra[2 * gi + 1][2 * gj];
            o[65] = Ra[2 * gi + 1][2 * gj + 1];
        }
    }
}

extern "C" void kernel_launch(void* const* d_in, const int* in_sizes, int n_in,
                              void* d_out, int out_size) {
    const float* spade = (const float*)d_in[0];
    const float* x     = (const float*)d_in[1];
    const float* w1    = (const float*)d_in[2];
    const float* b1    = (const float*)d_in[3];
    const float* w2    = (const float*)d_in[4];
    const float* b2    = (const float*)d_in[5];
    float* out = (float*)d_out;

    k_dot<<<dim3(32, NCHUNK), 256>>>(spade, x, w1, w2);
    k_reduce<<<128, 256>>>(b1, b2);
    k_match<<<512, 256>>>(out);
}